// round 10
// baseline (speedup 1.0000x reference)
#include <cuda_runtime.h>
#include <cuda_bf16.h>

// out = ((x*2 + 3 - 1) / 2)^2 == (x + 1)^2  (exact simplification in fp32)
//
// FINAL (converged, 9 rounds): HBM-bound streaming kernel at the GB300
// roofline. ~6.5 TB/s sustained (81-82% of 8 TB/s spec) on 512 MiB of
// mandatory fp32 read+write traffic -> ~74 us kernel time. Swept and
// falsified as non-binding: unroll depth (1/2/4/8), cache hints, MLP
// batching, predication, block size (256/512), grid shape (1184..32768
// CTAs), persistent vs one-shot launch. Three runs of THIS identical
// binary (R6/R8/R9) span the entire observed variance -> noise floor.
// Config: 256 threads, 4 x float4 per thread, one tile per CTA, .cs.

#define UNROLL 4
#define THREADS 256

__global__ void __launch_bounds__(THREADS) ew_sq_kernel(const float4* __restrict__ in,
                                                        float4* __restrict__ out,
                                                        int n4) {
    int i0 = blockIdx.x * (THREADS * UNROLL) + threadIdx.x;

    if (i0 + (UNROLL - 1) * THREADS < n4) {
        // Full tile: branch-free, loads front-batched (MLP=4).
        float4 v[UNROLL];
        #pragma unroll
        for (int k = 0; k < UNROLL; k++)
            v[k] = __ldcs(in + i0 + k * THREADS);
        #pragma unroll
        for (int k = 0; k < UNROLL; k++) {
            float a = v[k].x + 1.0f;
            float b = v[k].y + 1.0f;
            float c = v[k].z + 1.0f;
            float d = v[k].w + 1.0f;
            float4 r;
            r.x = a * a; r.y = b * b; r.z = c * c; r.w = d * d;
            __stcs(out + i0 + k * THREADS, r);
        }
    } else {
        // Only the single ragged last CTA takes this path.
        #pragma unroll
        for (int k = 0; k < UNROLL; k++) {
            int i = i0 + k * THREADS;
            if (i < n4) {
                float4 v = __ldcs(in + i);
                float a = v.x + 1.0f, b = v.y + 1.0f, c = v.z + 1.0f, d = v.w + 1.0f;
                float4 r; r.x = a * a; r.y = b * b; r.z = c * c; r.w = d * d;
                __stcs(out + i, r);
            }
        }
    }
}

// Scalar tail for element counts not divisible by 4 (unused for 8192^2).
__global__ void ew_sq_tail(const float* __restrict__ in, float* __restrict__ out,
                           int start, int n) {
    int i = start + blockIdx.x * blockDim.x + threadIdx.x;
    if (i < n) {
        float t = in[i] + 1.0f;
        out[i] = t * t;
    }
}

extern "C" void kernel_launch(void* const* d_in, const int* in_sizes, int n_in,
                              void* d_out, int out_size) {
    const float* x = (const float*)d_in[0];
    float* out = (float*)d_out;
    int n = in_sizes[0];

    int n4 = n / 4;
    int tail_start = n4 * 4;

    int blocks = (n4 + THREADS * UNROLL - 1) / (THREADS * UNROLL);
    if (blocks < 1) blocks = 1;

    if (n4 > 0) {
        ew_sq_kernel<<<blocks, THREADS>>>((const float4*)x, (float4*)out, n4);
    }
    if (tail_start < n) {
        int tail_n = n - tail_start;
        ew_sq_tail<<<(tail_n + 255) / 256, 256>>>(x, out, tail_start, n);
    }
}

// round 11
// speedup vs baseline: 1.0039x; 1.0039x over previous
#include <cuda_runtime.h>
#include <cuda_bf16.h>

// out = ((x*2 + 3 - 1) / 2)^2 == (x + 1)^2  (exact simplification in fp32)
//
// FINAL (converged, 10 rounds): HBM-bound streaming kernel at the GB300
// roofline. ~6.5 TB/s sustained (81-82% of 8 TB/s spec) on 512 MiB of
// mandatory fp32 read+write traffic -> ~74 us kernel time. Swept and
// falsified as non-binding: unroll depth (1/2/4/8), cache hints, MLP
// batching, predication, block size (256/512), grid shape (1184..32768
// CTAs), persistent vs one-shot launch. Four runs of THIS identical
// binary (R6/R8/R9/R10) span 81.63-82.08 us total -> pure noise floor;
// kernel DRAM% locked at 81-82.3% throughout. No unexploited lever:
// issue 8.5% (so 256b vector loads gain nothing), LTS cap is
// path-independent (so TMA gains nothing), traffic is dtype-minimal.
// Config: 256 threads, 4 x float4 per thread, one tile per CTA, .cs.

#define UNROLL 4
#define THREADS 256

__global__ void __launch_bounds__(THREADS) ew_sq_kernel(const float4* __restrict__ in,
                                                        float4* __restrict__ out,
                                                        int n4) {
    int i0 = blockIdx.x * (THREADS * UNROLL) + threadIdx.x;

    if (i0 + (UNROLL - 1) * THREADS < n4) {
        // Full tile: branch-free, loads front-batched (MLP=4).
        float4 v[UNROLL];
        #pragma unroll
        for (int k = 0; k < UNROLL; k++)
            v[k] = __ldcs(in + i0 + k * THREADS);
        #pragma unroll
        for (int k = 0; k < UNROLL; k++) {
            float a = v[k].x + 1.0f;
            float b = v[k].y + 1.0f;
            float c = v[k].z + 1.0f;
            float d = v[k].w + 1.0f;
            float4 r;
            r.x = a * a; r.y = b * b; r.z = c * c; r.w = d * d;
            __stcs(out + i0 + k * THREADS, r);
        }
    } else {
        // Only the single ragged last CTA takes this path.
        #pragma unroll
        for (int k = 0; k < UNROLL; k++) {
            int i = i0 + k * THREADS;
            if (i < n4) {
                float4 v = __ldcs(in + i);
                float a = v.x + 1.0f, b = v.y + 1.0f, c = v.z + 1.0f, d = v.w + 1.0f;
                float4 r; r.x = a * a; r.y = b * b; r.z = c * c; r.w = d * d;
                __stcs(out + i, r);
            }
        }
    }
}

// Scalar tail for element counts not divisible by 4 (unused for 8192^2).
__global__ void ew_sq_tail(const float* __restrict__ in, float* __restrict__ out,
                           int start, int n) {
    int i = start + blockIdx.x * blockDim.x + threadIdx.x;
    if (i < n) {
        float t = in[i] + 1.0f;
        out[i] = t * t;
    }
}

extern "C" void kernel_launch(void* const* d_in, const int* in_sizes, int n_in,
                              void* d_out, int out_size) {
    const float* x = (const float*)d_in[0];
    float* out = (float*)d_out;
    int n = in_sizes[0];

    int n4 = n / 4;
    int tail_start = n4 * 4;

    int blocks = (n4 + THREADS * UNROLL - 1) / (THREADS * UNROLL);
    if (blocks < 1) blocks = 1;

    if (n4 > 0) {
        ew_sq_kernel<<<blocks, THREADS>>>((const float4*)x, (float4*)out, n4);
    }
    if (tail_start < n) {
        int tail_n = n - tail_start;
        ew_sq_tail<<<(tail_n + 255) / 256, 256>>>(x, out, tail_start, n);
    }
}